// round 13
// baseline (speedup 1.0000x reference)
#include <cuda_runtime.h>
#include <cuda_fp16.h>
#include <cstdint>

// Problem constants
#define NB    32
#define CIN   128
#define HH    112
#define WW    112
#define COUT  256
#define TH    8
#define TW    16

// SMEM: input patch only (128 ch, 10x18 cells, 272B cells -> conflict-free ldsm)
#define P_CELL   272
#define P_COLS   18
#define P_ROWS   10
#define P_BYTES  (P_ROWS * P_COLS * P_CELL)   // 48960
#define S_TOTAL  P_BYTES

// Fragment-major fp16 weights:
// uint4 index = ((((ocg*9+tap)*8+k16)*2+wm)*4+mt)*32 + lane
__device__ uint4 g_wF[2 * 9 * 8 * 2 * 4 * 32];   // 36864 uint4 = 576 KB

// ---------------------------------------------------------------------------
// Helpers
// ---------------------------------------------------------------------------
__device__ __forceinline__ uint32_t smem_u32(const void* p) {
    uint32_t a;
    asm("{ .reg .u64 t; cvta.to.shared.u64 t, %1; cvt.u32.u64 %0, t; }"
        : "=r"(a) : "l"(p));
    return a;
}
__device__ __forceinline__ void ldsm4(uint32_t* r, uint32_t addr) {
    asm volatile("ldmatrix.sync.aligned.m8n8.x4.shared.b16 {%0,%1,%2,%3}, [%4];"
                 : "=r"(r[0]), "=r"(r[1]), "=r"(r[2]), "=r"(r[3]) : "r"(addr));
}
__device__ __forceinline__ void mma16816(float* d, uint4 a, const uint32_t* b) {
    asm volatile(
        "mma.sync.aligned.m16n8k16.row.col.f32.f16.f16.f32 "
        "{%0,%1,%2,%3}, {%4,%5,%6,%7}, {%8,%9}, {%0,%1,%2,%3};"
        : "+f"(d[0]), "+f"(d[1]), "+f"(d[2]), "+f"(d[3])
        : "r"(a.x), "r"(a.y), "r"(a.z), "r"(a.w), "r"(b[0]), "r"(b[1]));
}
__device__ __forceinline__ uint32_t pkh(float a, float b) {
    __half ha = __float2half_rn(a), hb = __float2half_rn(b);
    return (uint32_t)__half_as_ushort(ha) |
           ((uint32_t)__half_as_ushort(hb) << 16);
}

// ---------------------------------------------------------------------------
// Kernel 1: write fragment-major fp16 weights.
// Fragment regs follow the PTX mma.m16n8k16 A layout:
//   row0 = mt*16 + lane/4, cols c0 = k16*16 + (lane%4)*2
//   x={r0,c0|c0+1} y={r0+8,c0|c0+1} z={r0,c0+8|c0+9} w={r0+8,c0+8|c0+9}
// ---------------------------------------------------------------------------
__global__ void wprep_kernel(const float* __restrict__ w) {
    int j = blockIdx.x * blockDim.x + threadIdx.x;
    if (j >= 36864) return;
    const int lane = j & 31;
    const int mt   = (j >> 5) & 3;
    const int wm   = (j >> 7) & 1;
    const int k16  = (j >> 8) & 7;
    const int tj   = j >> 11;            // ocg*9 + tap
    const int ocg  = tj / 9;
    const int tap  = tj - ocg * 9;

    const int oc0 = ocg * 128 + wm * 64 + mt * 16 + (lane >> 2);
    const int c0  = k16 * 16 + (lane & 3) * 2;

    auto W = [&](int oc, int c) -> float {
        return w[((size_t)oc * CIN + c) * 9 + tap];
    };
    uint4 v;
    v.x = pkh(W(oc0,     c0),     W(oc0,     c0 + 1));
    v.y = pkh(W(oc0 + 8, c0),     W(oc0 + 8, c0 + 1));
    v.z = pkh(W(oc0,     c0 + 8), W(oc0,     c0 + 9));
    v.w = pkh(W(oc0 + 8, c0 + 8), W(oc0 + 8, c0 + 9));
    g_wF[j] = v;
}

// ---------------------------------------------------------------------------
// Kernel 2: implicit-GEMM conv, single-stream fp16 MMA.
// A fragments via direct coalesced LDG.128 from fragment-major weights:
// NO smem staging for A, NO cp.async, and a mainloop with ZERO barriers
// (single __syncthreads after the one-time patch build).
// grid = (98, 32, 2), block = 256, 2 CTAs/SM
// ---------------------------------------------------------------------------
extern __shared__ unsigned char smem[];

__global__ __launch_bounds__(256, 2)
void conv_mma_kernel(const float* __restrict__ in,
                     const float* __restrict__ bias,
                     float* __restrict__ out) {
    const int tid = threadIdx.x;
    const int wid = tid >> 5;
    const int lid = tid & 31;
    const int wm  = wid & 1;           // M half (64 oc)
    const int wn  = wid >> 1;          // N quarter (32 px)

    const int n   = blockIdx.y;
    const int ocg = blockIdx.z;
    const int h0  = (blockIdx.x / 7) * TH;
    const int w0  = (blockIdx.x % 7) * TW;

    const uint32_t sb = smem_u32(smem);

    // ---- accumulators, bias-initialized ----
    float acc[4][4][4];
    {
        const int r0 = lid >> 2;
#pragma unroll
        for (int mt = 0; mt < 4; ++mt) {
            const int oc0 = ocg * 128 + wm * 64 + mt * 16 + r0;
            const float b0 = __ldg(&bias[oc0]);
            const float b1 = __ldg(&bias[oc0 + 8]);
#pragma unroll
            for (int nt = 0; nt < 4; ++nt) {
                acc[mt][nt][0] = b0; acc[mt][nt][1] = b0;
                acc[mt][nt][2] = b1; acc[mt][nt][3] = b1;
            }
        }
    }

    // ---- per-lane B ldmatrix address components (validated R6-R12) ----
    const int nb_n   = (lid & 7) + ((lid >> 4) << 3);
    const uint32_t khoff = (uint32_t)(((lid >> 3) & 1) * 16);
    const int px0 = wn * 32 + nb_n;
    const int px1 = px0 + 16;
    const uint32_t bc0 =
        sb + (uint32_t)(((px0 >> 4) * P_COLS + (px0 & 15)) * P_CELL) + khoff;
    const uint32_t bc1 =
        sb + (uint32_t)(((px1 >> 4) * P_COLS + (px1 & 15)) * P_CELL) + khoff;

    // ---- A fragment base pointer (fragment-major global layout) ----
    const uint4* fb = g_wF + (size_t)ocg * 18432 + wm * 128 + lid;

    const float* inb = in + (size_t)n * CIN * HH * WW;

    // ---- patch build (all 128 ch), 90 elements/thread, incremental counters ----
    {
        int cc = tid / 180;
        int rm = tid - cc * 180;
        int yy = rm / 18;
        int xx = rm - yy * 18;
        for (int k = 0; k < 90; ++k) {
            const int gy = h0 - 1 + yy;
            const int gx = w0 - 1 + xx;
            float v = 0.0f;
            if (gy >= 0 && gy < HH && gx >= 0 && gx < WW)
                v = __ldg(&inb[((size_t)cc * HH + gy) * WW + gx]);
            const uint32_t cell =
                (uint32_t)((yy * P_COLS + xx) * P_CELL + cc * 2);
            *(__half*)(smem + cell) = __float2half_rn(v);
            // advance by 256 = 1*180 + 76 (76 = 4*18 + 4)
            cc += 1; yy += 4; xx += 4;
            if (xx >= 18) { xx -= 18; yy += 1; }
            if (yy >= 10) { yy -= 10; cc += 1; }
        }
    }
    __syncthreads();   // the ONLY barrier: patch visible to all warps

    // ---- barrier-free mainloop: u = tap*8 + k16, 72 iterations ----
#pragma unroll 4
    for (int u = 0; u < 72; ++u) {
        const int tap = u >> 3;
        const int kh  = tap / 3;
        const int kw  = tap - kh * 3;
        const uint32_t toff = (uint32_t)((kh * P_COLS + kw) * P_CELL);
        const uint32_t bkb  = (uint32_t)((u & 7) * 32);

        // A fragments: 4 coalesced LDG.128 (512B per warp each)
        uint4 af[4];
#pragma unroll
        for (int mt = 0; mt < 4; ++mt)
            af[mt] = __ldg(fb + (size_t)u * 256 + mt * 32);

        // B fragments from the patch
        uint32_t bf[8];
        ldsm4(bf,     bc0 + toff + bkb);
        ldsm4(bf + 4, bc1 + toff + bkb);

#pragma unroll
        for (int mt = 0; mt < 4; ++mt)
#pragma unroll
            for (int nt = 0; nt < 4; ++nt)
                mma16816(acc[mt][nt], af[mt], bf + nt * 2);
    }

    // ---- epilogue: direct register -> global stores ----
    {
        const int r0 = lid >> 2;
        const int cp = (lid & 3) * 2;
#pragma unroll
        for (int mt = 0; mt < 4; ++mt) {
            const int oc0 = ocg * 128 + wm * 64 + mt * 16 + r0;
            float* ob0 = out + (((size_t)n * COUT + oc0) * HH + h0) * WW + w0;
            float* ob1 = ob0 + (size_t)8 * HH * WW;
#pragma unroll
            for (int nt = 0; nt < 4; ++nt) {
                const int px = wn * 32 + nt * 8 + cp;
                const int py = px >> 4;
                const int pw = px & 15;
                const size_t o = (size_t)py * WW + pw;
                *(float2*)(ob0 + o) = make_float2(acc[mt][nt][0], acc[mt][nt][1]);
                *(float2*)(ob1 + o) = make_float2(acc[mt][nt][2], acc[mt][nt][3]);
            }
        }
    }
}

// ---------------------------------------------------------------------------
// Launch
// ---------------------------------------------------------------------------
extern "C" void kernel_launch(void* const* d_in, const int* in_sizes, int n_in,
                              void* d_out, int out_size) {
    const float* input  = (const float*)d_in[0];   // (32,128,112,112)
    const float* weight = (const float*)d_in[1];   // (256,128,3,3)
    const float* bias   = (const float*)d_in[2];   // (256,)
    float* out = (float*)d_out;                    // (32,256,112,112)

    static bool configured = false;
    if (!configured) {
        cudaFuncSetAttribute(conv_mma_kernel,
                             cudaFuncAttributeMaxDynamicSharedMemorySize,
                             S_TOTAL);
        configured = true;
    }

    wprep_kernel<<<(36864 + 255) / 256, 256>>>(weight);

    dim3 grid(14 * 7, NB, 2);   // 98 x 32 x 2
    conv_mma_kernel<<<grid, 256, S_TOTAL>>>(input, bias, out);
}